// round 6
// baseline (speedup 1.0000x reference)
#include <cuda_runtime.h>
#include <math.h>
#include <stdint.h>

#define T_ 1024
#define C_ 1024
#define B_ 4
#define H_ 16
#define L_ 12
#define V_ 50304
#define M_ 4096   // B*T tokens

// ======================= scratch (device globals) =======================
__device__ float g_x[(size_t)M_ * C_];
__device__ float g_big[(size_t)M_ * 4 * C_];
__device__ float g_logits[(size_t)M_ * V_];
__device__ float g_sa[M_];                       // per-row activation scales
__device__ signed char g_a8h[(size_t)M_ * 4 * C_];
__device__ signed char g_a8l[(size_t)M_ * 4 * C_];
// int8 split weights, transposed to [N,K], + per-output-channel scales
__device__ signed char g_qkvo8h[(size_t)4 * L_ * C_ * C_];
__device__ signed char g_qkvo8l[(size_t)4 * L_ * C_ * C_];
__device__ signed char g_w18h[(size_t)L_ * C_ * 4 * C_];
__device__ signed char g_w18l[(size_t)L_ * C_ * 4 * C_];
__device__ signed char g_w28h[(size_t)L_ * 4 * C_ * C_];
__device__ signed char g_w28l[(size_t)L_ * 4 * C_ * C_];
__device__ signed char g_wlm8h[(size_t)V_ * C_];
__device__ signed char g_wlm8l[(size_t)V_ * C_];
__device__ float g_s_qkvo[4 * L_ * C_];
__device__ float g_s_w1[L_ * 4 * C_];
__device__ float g_s_w2[L_ * C_];
__device__ float g_s_wlm[V_];

// ======================= asm helpers =======================
__device__ __forceinline__ uint32_t smem_u32(const void* p) {
    uint32_t a;
    asm("{ .reg .u64 t; cvta.to.shared.u64 t, %1; cvt.u32.u64 %0, t; }" : "=r"(a) : "l"(p));
    return a;
}
__device__ __forceinline__ void mma_s8(int* d, const uint32_t* a, uint32_t b0, uint32_t b1) {
    asm volatile(
        "mma.sync.aligned.m16n8k32.row.col.s32.s8.s8.s32 "
        "{%0,%1,%2,%3}, {%4,%5,%6,%7}, {%8,%9}, {%0,%1,%2,%3};"
        : "+r"(d[0]), "+r"(d[1]), "+r"(d[2]), "+r"(d[3])
        : "r"(a[0]), "r"(a[1]), "r"(a[2]), "r"(a[3]), "r"(b0), "r"(b1));
}
#define CP_ASYNC16(dst, src) \
    asm volatile("cp.async.cg.shared.global [%0], [%1], 16;" :: "r"(dst), "l"(src))
#define CP_COMMIT() asm volatile("cp.async.commit_group;")
#define CP_WAIT2()  asm volatile("cp.async.wait_group 2;")

// ======================= weight quantization ==========================
// per-output-channel (n) scale over K: s = max_k |W[k,n]| / 127
__global__ __launch_bounds__(128) void colmax_kernel(
    const float* __restrict__ W, int K, int N, float* __restrict__ s)
{
    size_t lsz = (size_t)K * N;
    const float* Wl = W + (size_t)blockIdx.z * lsz;
    float* sl = s + (size_t)blockIdx.z * N;
    int n = blockIdx.x * 128 + threadIdx.x;
    float m = 0.f;
    for (int k = 0; k < K; k++) m = fmaxf(m, fabsf(Wl[(size_t)k * N + n]));
    sl[n] = fmaxf(m, 1e-20f) * (1.0f / 127.0f);
}

// W [K,N] fp32 -> transpose + 2-digit int8 quantize: [N,K] h,l
__global__ __launch_bounds__(256) void wsplit8_kernel(
    const float* __restrict__ W, const float* __restrict__ sc,
    signed char* __restrict__ qh, signed char* __restrict__ ql, int K, int N)
{
    __shared__ float t[32][33];
    size_t lsz = (size_t)K * N;
    const float* Wl = W + (size_t)blockIdx.z * lsz;
    const float* scl = sc + (size_t)blockIdx.z * N;
    signed char* qhl = qh + (size_t)blockIdx.z * lsz;
    signed char* qll = ql + (size_t)blockIdx.z * lsz;
    int n0 = blockIdx.x * 32, k0 = blockIdx.y * 32;
    int tx = threadIdx.x & 31, ty = threadIdx.x >> 5;
    #pragma unroll
    for (int i = 0; i < 4; i++)
        t[ty + 8 * i][tx] = Wl[(size_t)(k0 + ty + 8 * i) * N + n0 + tx];
    __syncthreads();
    #pragma unroll
    for (int i = 0; i < 4; i++) {
        int n = n0 + ty + 8 * i;
        float s = scl[n];
        float inv = 1.0f / s;
        float v = t[tx][ty + 8 * i];
        float h = rintf(v * inv);
        h = fminf(fmaxf(h, -127.f), 127.f);
        float r = v - h * s;
        float l = rintf(r * inv * 128.f);
        l = fminf(fmaxf(l, -127.f), 127.f);
        size_t off = (size_t)n * K + k0 + tx;
        qhl[off] = (signed char)(int)h;
        qll[off] = (signed char)(int)l;
    }
}

// ======================= INT8 GEMM ====================================
// C[M,N] = sA[m]*sW[n]*(HH + ML/128) (+bias,+resid,relu)
// CTA 128x64, 8 warps (4m x 2n), warp 32x32. K-chunk 64, 3-stage B ring.
#define QRS 80                        // B smem row stride (64 data + 16 pad)
#define QSTG (2 * 64 * QRS)           // Bh + Bl per stage = 10240
#define QBL 5120                      // Bl offset within stage

template <int BIAS, int RELU, int RESID>
__global__ __launch_bounds__(256, 2) void gemm_s8(
    const signed char* __restrict__ Ah, const signed char* __restrict__ Al,
    const float* __restrict__ sA,
    const signed char* __restrict__ Bh, const signed char* __restrict__ Bl,
    const float* __restrict__ sW,
    const float* __restrict__ bias, const float* __restrict__ resid,
    float* __restrict__ C, int N, int K)
{
    __shared__ char sm[3 * QSTG];
    uint32_t sb = smem_u32(sm);
    int tid = threadIdx.x;
    int lane = tid & 31, wid = tid >> 5;
    int warp_m = wid >> 1, warp_n = wid & 1;
    int m0 = blockIdx.x * 128, n0 = blockIdx.y * 64;
    const int NC = K >> 6;

    int hh[2][4][4], ml[2][4][4];
    #pragma unroll
    for (int t = 0; t < 2; t++)
        #pragma unroll
        for (int n = 0; n < 4; n++)
            #pragma unroll
            for (int j = 0; j < 4; j++) { hh[t][n][j] = 0; ml[t][n][j] = 0; }

    int aRow = m0 + warp_m * 32 + (lane >> 2);
    const signed char* AhB = Ah + (size_t)aRow * K + ((lane & 3) << 2);
    const signed char* AlB = Al + (size_t)aRow * K + ((lane & 3) << 2);

    auto issueB = [&](int c, int s) {
        int k0 = c << 6;
        int row = tid >> 2, seg = (tid & 3) << 4;
        uint32_t d = sb + s * QSTG + row * QRS + seg;
        CP_ASYNC16(d, Bh + (size_t)(n0 + row) * K + k0 + seg);
        CP_ASYNC16(d + QBL, Bl + (size_t)(n0 + row) * K + k0 + seg);
        CP_COMMIT();
    };

    auto compute = [&](int c, int s) {
        #pragma unroll
        for (int ks = 0; ks < 2; ks++) {
            int kc = (c << 6) + (ks << 5);
            uint32_t ah[2][4], al[2][4];
            #pragma unroll
            for (int t = 0; t < 2; t++) {
                size_t o = (size_t)(t * 16) * K + kc;
                ah[t][0] = *(const uint32_t*)(AhB + o);
                ah[t][1] = *(const uint32_t*)(AhB + o + (size_t)8 * K);
                ah[t][2] = *(const uint32_t*)(AhB + o + 16);
                ah[t][3] = *(const uint32_t*)(AhB + o + (size_t)8 * K + 16);
                al[t][0] = *(const uint32_t*)(AlB + o);
                al[t][1] = *(const uint32_t*)(AlB + o + (size_t)8 * K);
                al[t][2] = *(const uint32_t*)(AlB + o + 16);
                al[t][3] = *(const uint32_t*)(AlB + o + (size_t)8 * K + 16);
            }
            #pragma unroll
            for (int nt = 0; nt < 4; nt++) {
                const char* bb = sm + s * QSTG +
                    (warp_n * 32 + nt * 8 + (lane >> 2)) * QRS + (ks << 5) + ((lane & 3) << 2);
                uint32_t bh0 = *(const uint32_t*)(bb);
                uint32_t bh1 = *(const uint32_t*)(bb + 16);
                uint32_t bl0 = *(const uint32_t*)(bb + QBL);
                uint32_t bl1 = *(const uint32_t*)(bb + QBL + 16);
                #pragma unroll
                for (int t = 0; t < 2; t++) {
                    mma_s8(hh[t][nt], ah[t], bh0, bh1);
                    mma_s8(ml[t][nt], al[t], bh0, bh1);
                    mma_s8(ml[t][nt], ah[t], bl0, bl1);
                }
            }
        }
    };

    issueB(0, 0);
    issueB(1, 1);
    issueB(2, 2);

    for (int c = 0; c < NC; c++) {
        int s = c % 3;
        CP_WAIT2();
        __syncthreads();
        compute(c, s);
        __syncthreads();
        if (c + 3 < NC) issueB(c + 3, s);
    }

    // ---- epilogue ----
    #pragma unroll
    for (int t = 0; t < 2; t++) {
        int r0 = m0 + warp_m * 32 + t * 16 + (lane >> 2);
        float sa0 = sA[r0], sa1 = sA[r0 + 8];
        #pragma unroll
        for (int nt = 0; nt < 4; nt++) {
            int c0 = n0 + warp_n * 32 + nt * 8 + ((lane & 3) << 1);
            float sw0 = sW[c0], sw1 = sW[c0 + 1];
            float v0 = sa0 * sw0 * ((float)hh[t][nt][0] + (float)ml[t][nt][0] * 0.0078125f);
            float v1 = sa0 * sw1 * ((float)hh[t][nt][1] + (float)ml[t][nt][1] * 0.0078125f);
            float v2 = sa1 * sw0 * ((float)hh[t][nt][2] + (float)ml[t][nt][2] * 0.0078125f);
            float v3 = sa1 * sw1 * ((float)hh[t][nt][3] + (float)ml[t][nt][3] * 0.0078125f);
            if (BIAS) {
                float b0 = bias[c0], b1 = bias[c0 + 1];
                v0 += b0; v1 += b1; v2 += b0; v3 += b1;
            }
            size_t o0 = (size_t)r0 * N + c0;
            size_t o1 = (size_t)(r0 + 8) * N + c0;
            if (RESID) {
                float2 q0 = *(const float2*)(resid + o0);
                float2 q1 = *(const float2*)(resid + o1);
                v0 += q0.x; v1 += q0.y; v2 += q1.x; v3 += q1.y;
            }
            if (RELU) {
                v0 = fmaxf(v0, 0.f); v1 = fmaxf(v1, 0.f);
                v2 = fmaxf(v2, 0.f); v3 = fmaxf(v3, 0.f);
            }
            *(float2*)(C + o0) = make_float2(v0, v1);
            *(float2*)(C + o1) = make_float2(v2, v3);
        }
    }
}

// ======================= embedding ====================================
__global__ __launch_bounds__(256) void embed_kernel(
    const int* __restrict__ idx, const float* __restrict__ tok,
    const float* __restrict__ pos, float* __restrict__ x)
{
    int bt = blockIdx.x;
    int t = bt & (T_ - 1);
    int token = idx[bt];
    int c = threadIdx.x * 4;
    float4 tv = *(const float4*)(tok + (size_t)token * C_ + c);
    float4 pv = *(const float4*)(pos + (size_t)t * C_ + c);
    *(float4*)(x + (size_t)bt * C_ + c) =
        make_float4(tv.x + pv.x, tv.y + pv.y, tv.z + pv.z, tv.w + pv.w);
}

// ======================= fused layernorm + quantize ===================
__global__ __launch_bounds__(256) void ln_quant_kernel(
    const float* __restrict__ x, const float* __restrict__ g,
    const float* __restrict__ b, signed char* __restrict__ qh,
    signed char* __restrict__ ql, float* __restrict__ sa)
{
    __shared__ float red[8];
    __shared__ float bc0, bc1;
    int row = blockIdx.x, tid = threadIdx.x;
    const float* xr = x + (size_t)row * C_;
    float4 xv = *(const float4*)(xr + tid * 4);
    float s = xv.x + xv.y + xv.z + xv.w;
    #pragma unroll
    for (int o = 16; o; o >>= 1) s += __shfl_xor_sync(0xffffffffu, s, o);
    if ((tid & 31) == 0) red[tid >> 5] = s;
    __syncthreads();
    if (tid == 0) {
        float t = 0.f;
        #pragma unroll
        for (int i = 0; i < 8; i++) t += red[i];
        bc0 = t * (1.0f / C_);
    }
    __syncthreads();
    float mean = bc0;
    float d0 = xv.x - mean, d1 = xv.y - mean, d2 = xv.z - mean, d3 = xv.w - mean;
    float sq = d0 * d0 + d1 * d1 + d2 * d2 + d3 * d3;
    #pragma unroll
    for (int o = 16; o; o >>= 1) sq += __shfl_xor_sync(0xffffffffu, sq, o);
    if ((tid & 31) == 0) red[tid >> 5] = sq;
    __syncthreads();
    if (tid == 0) {
        float t = 0.f;
        #pragma unroll
        for (int i = 0; i < 8; i++) t += red[i];
        bc1 = rsqrtf(t * (1.0f / C_) + 1e-5f);
    }
    __syncthreads();
    float istd = bc1;
    float4 gv = *(const float4*)(g + tid * 4);
    float4 bv = *(const float4*)(b + tid * 4);
    float y0 = d0 * istd * gv.x + bv.x;
    float y1 = d1 * istd * gv.y + bv.y;
    float y2 = d2 * istd * gv.z + bv.z;
    float y3 = d3 * istd * gv.w + bv.w;

    // row max reduce
    float am = fmaxf(fmaxf(fabsf(y0), fabsf(y1)), fmaxf(fabsf(y2), fabsf(y3)));
    #pragma unroll
    for (int o = 16; o; o >>= 1) am = fmaxf(am, __shfl_xor_sync(0xffffffffu, am, o));
    if ((tid & 31) == 0) red[tid >> 5] = am;
    __syncthreads();
    if (tid == 0) {
        float t = red[0];
        #pragma unroll
        for (int i = 1; i < 8; i++) t = fmaxf(t, red[i]);
        t = fmaxf(t, 1e-20f);
        bc0 = t * (1.0f / 127.0f);
        bc1 = 127.0f / t;
        sa[row] = bc0;
    }
    __syncthreads();
    float qs = bc0, qi = bc1;
    float h0 = rintf(y0 * qi), h1 = rintf(y1 * qi), h2 = rintf(y2 * qi), h3 = rintf(y3 * qi);
    float l0 = rintf((y0 - h0 * qs) * qi * 128.f);
    float l1 = rintf((y1 - h1 * qs) * qi * 128.f);
    float l2 = rintf((y2 - h2 * qs) * qi * 128.f);
    float l3 = rintf((y3 - h3 * qs) * qi * 128.f);
    ((char4*)qh)[(size_t)row * 256 + tid] =
        make_char4((int)h0, (int)h1, (int)h2, (int)h3);
    ((char4*)ql)[(size_t)row * 256 + tid] =
        make_char4((int)l0, (int)l1, (int)l2, (int)l3);
}

// ======================= generic row quantize =========================
__global__ __launch_bounds__(256) void rowquant_kernel(
    const float* __restrict__ x, int Kw, signed char* __restrict__ qh,
    signed char* __restrict__ ql, float* __restrict__ sa)
{
    __shared__ float red[8];
    __shared__ float bc0, bc1;
    int row = blockIdx.x, tid = threadIdx.x;
    int nv = Kw >> 10;  // float4 groups per thread (1 or 4)
    const float4* xr = (const float4*)(x + (size_t)row * Kw);
    float4 vals[4];
    float am = 0.f;
    for (int i = 0; i < nv; i++) {
        float4 v = xr[tid + (i << 8)];
        vals[i] = v;
        am = fmaxf(am, fmaxf(fmaxf(fabsf(v.x), fabsf(v.y)), fmaxf(fabsf(v.z), fabsf(v.w))));
    }
    #pragma unroll
    for (int o = 16; o; o >>= 1) am = fmaxf(am, __shfl_xor_sync(0xffffffffu, am, o));
    if ((tid & 31) == 0) red[tid >> 5] = am;
    __syncthreads();
    if (tid == 0) {
        float t = red[0];
        #pragma unroll
        for (int i = 1; i < 8; i++) t = fmaxf(t, red[i]);
        t = fmaxf(t, 1e-20f);
        bc0 = t * (1.0f / 127.0f);
        bc1 = 127.0f / t;
        sa[row] = bc0;
    }
    __syncthreads();
    float qs = bc0, qi = bc1;
    char4* qh4 = (char4*)(qh + (size_t)row * Kw);
    char4* ql4 = (char4*)(ql + (size_t)row * Kw);
    for (int i = 0; i < nv; i++) {
        float4 v = vals[i];
        float h0 = rintf(v.x * qi), h1 = rintf(v.y * qi);
        float h2 = rintf(v.z * qi), h3 = rintf(v.w * qi);
        float l0 = rintf((v.x - h0 * qs) * qi * 128.f);
        float l1 = rintf((v.y - h1 * qs) * qi * 128.f);
        float l2 = rintf((v.z - h2 * qs) * qi * 128.f);
        float l3 = rintf((v.w - h3 * qs) * qi * 128.f);
        qh4[tid + (i << 8)] = make_char4((int)h0, (int)h1, (int)h2, (int)h3);
        ql4[tid + (i << 8)] = make_char4((int)l0, (int)l1, (int)l2, (int)l3);
    }
}

// ======================= causal flash attention (fp32) ================
#define ATTN_SMEM (4 * 64 * 68 * 4)
__global__ __launch_bounds__(256) void attn_kernel(
    const float* __restrict__ Q, const float* __restrict__ K,
    const float* __restrict__ V, float* __restrict__ O)
{
    extern __shared__ float smf[];
    float (*Qs)[68]  = (float(*)[68])smf;
    float (*KsT)[68] = (float(*)[68])(smf + 64 * 68);
    float (*Vs)[68]  = (float(*)[68])(smf + 2 * 64 * 68);
    float (*Ps)[68]  = (float(*)[68])(smf + 3 * 64 * 68);

    int qb = blockIdx.x;
    int bh = blockIdx.y;
    int b = bh >> 4, hh = bh & 15;
    size_t base = (size_t)b * T_ * C_ + (size_t)hh * 64;
    int tid = threadIdx.x;
    int row = tid >> 2, seg = tid & 3;
    int gq = qb * 64 + row;

    for (int i = tid; i < 64 * 16; i += 256) {
        int r = i >> 4, c4 = (i & 15) << 2;
        *(float4*)&Qs[r][c4] = *(const float4*)&Q[base + (size_t)(qb * 64 + r) * C_ + c4];
    }
    __syncthreads();

    float m = -1e30f, l = 0.f;
    float o[16];
    #pragma unroll
    for (int j = 0; j < 16; j++) o[j] = 0.f;

    for (int kb = 0; kb <= qb; kb++) {
        for (int i = tid; i < 64 * 16; i += 256) {
            int r = i >> 4, c4 = (i & 15) << 2;
            size_t goff = base + (size_t)(kb * 64 + r) * C_ + c4;
            float4 kv = *(const float4*)&K[goff];
            KsT[c4 + 0][r] = kv.x;
            KsT[c4 + 1][r] = kv.y;
            KsT[c4 + 2][r] = kv.z;
            KsT[c4 + 3][r] = kv.w;
            *(float4*)&Vs[r][c4] = *(const float4*)&V[goff];
        }
        __syncthreads();

        float sv[16];
        #pragma unroll
        for (int j = 0; j < 16; j++) sv[j] = 0.f;
        #pragma unroll 16
        for (int d = 0; d < 64; d++) {
            float qd = Qs[row][d];
            float4 k0 = *(const float4*)&KsT[d][seg * 16];
            float4 k1 = *(const float4*)&KsT[d][seg * 16 + 4];
            float4 k2 = *(const float4*)&KsT[d][seg * 16 + 8];
            float4 k3 = *(const float4*)&KsT[d][seg * 16 + 12];
            sv[0]  += qd * k0.x; sv[1]  += qd * k0.y; sv[2]  += qd * k0.z; sv[3]  += qd * k0.w;
            sv[4]  += qd * k1.x; sv[5]  += qd * k1.y; sv[6]  += qd * k1.z; sv[7]  += qd * k1.w;
            sv[8]  += qd * k2.x; sv[9]  += qd * k2.y; sv[10] += qd * k2.z; sv[11] += qd * k2.w;
            sv[12] += qd * k3.x; sv[13] += qd * k3.y; sv[14] += qd * k3.z; sv[15] += qd * k3.w;
        }
        #pragma unroll
        for (int j = 0; j < 16; j++) {
            int gk = kb * 64 + seg * 16 + j;
            sv[j] = (gk <= gq) ? sv[j] * 0.125f : -1e30f;
        }

        float tmax = sv[0];
        #pragma unroll
        for (int j = 1; j < 16; j++) tmax = fmaxf(tmax, sv[j]);
        tmax = fmaxf(tmax, __shfl_xor_sync(0xffffffffu, tmax, 1));
        tmax = fmaxf(tmax, __shfl_xor_sync(0xffffffffu, tmax, 2));
        float mnew = fmaxf(m, tmax);
        float corr = __expf(m - mnew);
        float ls = 0.f;
        #pragma unroll
        for (int j = 0; j < 16; j++) {
            float p = __expf(sv[j] - mnew);
            Ps[row][seg * 16 + j] = p;
            ls += p;
        }
        ls += __shfl_xor_sync(0xffffffffu, ls, 1);
        ls += __shfl_xor_sync(0xffffffffu, ls, 2);
        l = l * corr + ls;
        m = mnew;
        #pragma unroll
        for (int j = 0; j < 16; j++) o[j] *= corr;
        __syncwarp();

        #pragma unroll 8
        for (int kk = 0; kk < 64; kk++) {
            float p = Ps[row][kk];
            const float* vr = &Vs[kk][seg * 16];
            float4 v0 = *(const float4*)(vr);
            float4 v1 = *(const float4*)(vr + 4);
            float4 v2 = *(const float4*)(vr + 8);
            float4 v3 = *(const float4*)(vr + 12);
            o[0]  += p * v0.x; o[1]  += p * v0.y; o[2]  += p * v0.z; o[3]  += p * v0.w;
            o[4]  += p * v1.x; o[5]  += p * v1.y; o[6]  += p * v1.z; o[7]  += p * v1.w;
            o[8]  += p * v2.x; o[9]  += p * v2.y; o[10] += p * v2.z; o[11] += p * v2.w;
            o[12] += p * v3.x; o[13] += p * v3.y; o[14] += p * v3.z; o[15] += p * v3.w;
        }
        __syncthreads();
    }

    float inv = 1.0f / l;
    size_t ooff = base + (size_t)gq * C_ + seg * 16;
    *(float4*)&O[ooff]      = make_float4(o[0] * inv,  o[1] * inv,  o[2] * inv,  o[3] * inv);
    *(float4*)&O[ooff + 4]  = make_float4(o[4] * inv,  o[5] * inv,  o[6] * inv,  o[7] * inv);
    *(float4*)&O[ooff + 8]  = make_float4(o[8] * inv,  o[9] * inv,  o[10] * inv, o[11] * inv);
    *(float4*)&O[ooff + 12] = make_float4(o[12] * inv, o[13] * inv, o[14] * inv, o[15] * inv);
}

// ======================= loss =========================================
__global__ void loss_init_kernel(float* loss) { *loss = 0.f; }

__global__ __launch_bounds__(256) void loss_kernel(
    const float* __restrict__ logits, const int* __restrict__ targets,
    float* __restrict__ loss)
{
    __shared__ float red[8];
    __shared__ float bmx_s, bsum_s;
    int row = blockIdx.x, tid = threadIdx.x;
    const float4* lr4 = (const float4*)(logits + (size_t)row * V_);

    float mx = -1e30f;
    for (int i = tid; i < V_ / 4; i += 256) {
        float4 u = lr4[i];
        mx = fmaxf(mx, fmaxf(fmaxf(u.x, u.y), fmaxf(u.z, u.w)));
    }
    #pragma unroll
    for (int o = 16; o; o >>= 1) mx = fmaxf(mx, __shfl_xor_sync(0xffffffffu, mx, o));
    if ((tid & 31) == 0) red[tid >> 5] = mx;
    __syncthreads();
    if (tid == 0) {
        float t = red[0];
        #pragma unroll
        for (int i = 1; i < 8; i++) t = fmaxf(t, red[i]);
        bmx_s = t;
    }
    __syncthreads();
    float bmx = bmx_s;

    float s = 0.f;
    for (int i = tid; i < V_ / 4; i += 256) {
        float4 u = lr4[i];
        s += __expf(u.x - bmx) + __expf(u.y - bmx) + __expf(u.z - bmx) + __expf(u.w - bmx);
    }
    #pragma unroll
    for (int o = 16; o; o >>= 1) s += __shfl_xor_sync(0xffffffffu, s, o);
    if ((tid & 31) == 0) red[tid >> 5] = s;
    __syncthreads();
    if (tid == 0) {
        float t = 0.f;
        #pragma unroll
        for (int i = 0; i < 8; i++) t += red[i];
        bsum_s = t;
    }
    __syncthreads();
    if (tid == 0) {
        int tgt = targets[row];
        float lp = logits[(size_t)row * V_ + tgt] - bmx - logf(bsum_s);
        atomicAdd(loss, -lp * (1.0f / M_));
    }
}

// ======================= host =========================================
extern "C" void kernel_launch(void* const* d_in, const int* in_sizes, int n_in,
                              void* d_out, int out_size)
{
    const int*   idx     = (const int*)d_in[0];
    const int*   targets = (const int*)d_in[1];
    const float* tok     = (const float*)d_in[2];
    const float* pos     = (const float*)d_in[3];
    const float* ln1g    = (const float*)d_in[4];
    const float* ln1b    = (const float*)d_in[5];
    const float* Wq      = (const float*)d_in[6];
    const float* Wk      = (const float*)d_in[7];
    const float* Wv      = (const float*)d_in[8];
    const float* Wo      = (const float*)d_in[9];
    const float* bo      = (const float*)d_in[10];
    const float* ln2g    = (const float*)d_in[11];
    const float* ln2b    = (const float*)d_in[12];
    const float* W1      = (const float*)d_in[13];
    const float* b1      = (const float*)d_in[14];
    const float* W2      = (const float*)d_in[15];
    const float* b2      = (const float*)d_in[16];
    const float* lnfg    = (const float*)d_in[17];
    const float* lnfb    = (const float*)d_in[18];
    const float* Wlm     = (const float*)d_in[19];
    const float* blm     = (const float*)d_in[20];

    static float *x, *big, *lgbuf, *sa;
    static signed char *a8h, *a8l, *qk8h, *qk8l, *w18h, *w18l, *w28h, *w28l, *lm8h, *lm8l;
    static float *s_qkvo, *s_w1, *s_w2, *s_wlm;
    static bool init = false;
    if (!init) {
        cudaGetSymbolAddress((void**)&x, g_x);
        cudaGetSymbolAddress((void**)&big, g_big);
        cudaGetSymbolAddress((void**)&lgbuf, g_logits);
        cudaGetSymbolAddress((void**)&sa, g_sa);
        cudaGetSymbolAddress((void**)&a8h, g_a8h);
        cudaGetSymbolAddress((void**)&a8l, g_a8l);
        cudaGetSymbolAddress((void**)&qk8h, g_qkvo8h);
        cudaGetSymbolAddress((void**)&qk8l, g_qkvo8l);
        cudaGetSymbolAddress((void**)&w18h, g_w18h);
        cudaGetSymbolAddress((void**)&w18l, g_w18l);
        cudaGetSymbolAddress((void**)&w28h, g_w28h);
        cudaGetSymbolAddress((void**)&w28l, g_w28l);
        cudaGetSymbolAddress((void**)&lm8h, g_wlm8h);
        cudaGetSymbolAddress((void**)&lm8l, g_wlm8l);
        cudaGetSymbolAddress((void**)&s_qkvo, g_s_qkvo);
        cudaGetSymbolAddress((void**)&s_w1, g_s_w1);
        cudaGetSymbolAddress((void**)&s_w2, g_s_w2);
        cudaGetSymbolAddress((void**)&s_wlm, g_s_wlm);
        cudaFuncSetAttribute(attn_kernel, cudaFuncAttributeMaxDynamicSharedMemorySize, ATTN_SMEM);
        init = true;
    }

    const size_t NTV = (size_t)M_ * V_;
    float* logits_ptr = ((size_t)out_size >= NTV) ? (float*)d_out : lgbuf;
    float* loss_ptr = nullptr;
    if ((size_t)out_size == NTV + 1)     loss_ptr = (float*)d_out + NTV;
    else if ((size_t)out_size < NTV)     loss_ptr = (float*)d_out;

    float* qb_  = big;
    float* kb_  = big + (size_t)M_ * C_;
    float* vb_  = big + (size_t)2 * M_ * C_;
    float* att_ = big + (size_t)3 * M_ * C_;
    float* mlp_ = big;

    const size_t CC = (size_t)C_ * C_;
    const size_t LCC = (size_t)L_ * CC;
    const size_t LC4 = (size_t)L_ * C_ * 4 * C_;

    // ---- weight prep: per-col scales + transpose/quantize ----
    colmax_kernel<<<dim3(C_ / 128, 1, L_), 128>>>(Wq, C_, C_, s_qkvo + 0 * L_ * C_);
    colmax_kernel<<<dim3(C_ / 128, 1, L_), 128>>>(Wk, C_, C_, s_qkvo + 1 * L_ * C_);
    colmax_kernel<<<dim3(C_ / 128, 1, L_), 128>>>(Wv, C_, C_, s_qkvo + 2 * L_ * C_);
    colmax_kernel<<<dim3(C_ / 128, 1, L_), 128>>>(Wo, C_, C_, s_qkvo + 3 * L_ * C_);
    colmax_kernel<<<dim3(4 * C_ / 128, 1, L_), 128>>>(W1, C_, 4 * C_, s_w1);
    colmax_kernel<<<dim3(C_ / 128, 1, L_), 128>>>(W2, 4 * C_, C_, s_w2);
    colmax_kernel<<<dim3(V_ / 128, 1, 1), 128>>>(Wlm, C_, V_, s_wlm);

    wsplit8_kernel<<<dim3(C_ / 32, C_ / 32, L_), 256>>>(Wq, s_qkvo + 0 * L_ * C_, qk8h + 0 * LCC, qk8l + 0 * LCC, C_, C_);
    wsplit8_kernel<<<dim3(C_ / 32, C_ / 32, L_), 256>>>(Wk, s_qkvo + 1 * L_ * C_, qk8h + 1 * LCC, qk8l + 1 * LCC, C_, C_);
    wsplit8_kernel<<<dim3(C_ / 32, C_ / 32, L_), 256>>>(Wv, s_qkvo + 2 * L_ * C_, qk8h + 2 * LCC, qk8l + 2 * LCC, C_, C_);
    wsplit8_kernel<<<dim3(C_ / 32, C_ / 32, L_), 256>>>(Wo, s_qkvo + 3 * L_ * C_, qk8h + 3 * LCC, qk8l + 3 * LCC, C_, C_);
    wsplit8_kernel<<<dim3(4 * C_ / 32, C_ / 32, L_), 256>>>(W1, s_w1, w18h, w18l, C_, 4 * C_);
    wsplit8_kernel<<<dim3(C_ / 32, 4 * C_ / 32, L_), 256>>>(W2, s_w2, w28h, w28l, 4 * C_, C_);
    wsplit8_kernel<<<dim3(V_ / 32, C_ / 32, 1), 256>>>(Wlm, s_wlm, lm8h, lm8l, C_, V_);

    dim3 g1(M_ / 128, C_ / 64);
    dim3 g4(M_ / 128, 4 * C_ / 64);
    dim3 gl(M_ / 128, V_ / 64);
    dim3 ga(T_ / 64, B_ * H_);

    embed_kernel<<<M_, 256>>>(idx, tok, pos, x);

    for (int l = 0; l < L_; l++) {
        size_t wo = (size_t)l * CC;
        size_t w1o = (size_t)l * CC * 4;
        ln_quant_kernel<<<M_, 256>>>(x, ln1g + (size_t)l * C_, ln1b + (size_t)l * C_, a8h, a8l, sa);
        gemm_s8<0,0,0><<<g1, 256>>>(a8h, a8l, sa, qk8h + 0 * LCC + wo, qk8l + 0 * LCC + wo,
                                    s_qkvo + 0 * L_ * C_ + l * C_, nullptr, nullptr, qb_, C_, C_);
        gemm_s8<0,0,0><<<g1, 256>>>(a8h, a8l, sa, qk8h + 1 * LCC + wo, qk8l + 1 * LCC + wo,
                                    s_qkvo + 1 * L_ * C_ + l * C_, nullptr, nullptr, kb_, C_, C_);
        gemm_s8<0,0,0><<<g1, 256>>>(a8h, a8l, sa, qk8h + 2 * LCC + wo, qk8l + 2 * LCC + wo,
                                    s_qkvo + 2 * L_ * C_ + l * C_, nullptr, nullptr, vb_, C_, C_);
        attn_kernel<<<ga, 256, ATTN_SMEM>>>(qb_, kb_, vb_, att_);
        rowquant_kernel<<<M_, 256>>>(att_, C_, a8h, a8l, sa);
        gemm_s8<1,0,1><<<g1, 256>>>(a8h, a8l, sa, qk8h + 3 * LCC + wo, qk8l + 3 * LCC + wo,
                                    s_qkvo + 3 * L_ * C_ + l * C_, bo + (size_t)l * C_, x, x, C_, C_);
        ln_quant_kernel<<<M_, 256>>>(x, ln2g + (size_t)l * C_, ln2b + (size_t)l * C_, a8h, a8l, sa);
        gemm_s8<1,1,0><<<g4, 256>>>(a8h, a8l, sa, w18h + w1o, w18l + w1o,
                                    s_w1 + l * 4 * C_, b1 + (size_t)l * 4 * C_, nullptr, mlp_, 4 * C_, C_);
        rowquant_kernel<<<M_, 256>>>(mlp_, 4 * C_, a8h, a8l, sa);
        gemm_s8<1,0,1><<<g1, 256>>>(a8h, a8l, sa, w28h + w1o, w28l + w1o,
                                    s_w2 + l * C_, b2 + (size_t)l * C_, x, x, C_, 4 * C_);
    }

    ln_quant_kernel<<<M_, 256>>>(x, lnfg, lnfb, a8h, a8l, sa);
    gemm_s8<1,0,0><<<gl, 256>>>(a8h, a8l, sa, lm8h, lm8l, s_wlm, blm, nullptr, logits_ptr, V_, C_);

    if (loss_ptr) {
        loss_init_kernel<<<1, 1>>>(loss_ptr);
        loss_kernel<<<M_, 256>>>(logits_ptr, targets, loss_ptr);
    }
}

// round 7
// speedup vs baseline: 1.7345x; 1.7345x over previous
#include <cuda_runtime.h>
#include <cuda_bf16.h>
#include <cuda_fp16.h>
#include <math.h>
#include <stdint.h>

#define T_ 1024
#define C_ 1024
#define B_ 4
#define H_ 16
#define L_ 12
#define V_ 50304
#define M_ 4096   // B*T tokens

// ======================= scratch (device globals) =======================
__device__ float g_x[(size_t)M_ * C_];
__device__ float g_h[(size_t)M_ * C_];
__device__ float g_big[(size_t)M_ * 4 * C_];
__device__ float g_logits[(size_t)M_ * V_];
// bf16 split weights, transposed to [N,K]
__device__ __nv_bfloat16 g_qkvo_hi[(size_t)4 * L_ * C_ * C_];
__device__ __nv_bfloat16 g_qkvo_lo[(size_t)4 * L_ * C_ * C_];
__device__ __nv_bfloat16 g_w1_hi[(size_t)L_ * C_ * 4 * C_];
__device__ __nv_bfloat16 g_w1_lo[(size_t)L_ * C_ * 4 * C_];
__device__ __nv_bfloat16 g_w2_hi[(size_t)L_ * 4 * C_ * C_];
__device__ __nv_bfloat16 g_w2_lo[(size_t)L_ * 4 * C_ * C_];
__device__ __half g_wlm16[(size_t)V_ * C_];   // fp16 single-digit LM head

// ======================= small asm helpers =======================
__device__ __forceinline__ uint32_t smem_u32(const void* p) {
    uint32_t a;
    asm("{ .reg .u64 t; cvta.to.shared.u64 t, %1; cvt.u32.u64 %0, t; }" : "=r"(a) : "l"(p));
    return a;
}
__device__ __forceinline__ void ldmatrix_x4(uint32_t* r, uint32_t addr) {
    asm volatile("ldmatrix.sync.aligned.m8n8.x4.shared.b16 {%0,%1,%2,%3}, [%4];"
        : "=r"(r[0]), "=r"(r[1]), "=r"(r[2]), "=r"(r[3]) : "r"(addr));
}
__device__ __forceinline__ void mma_bf16(float* d, const uint32_t* a, const uint32_t* b) {
    asm volatile(
        "mma.sync.aligned.m16n8k16.row.col.f32.bf16.bf16.f32 "
        "{%0,%1,%2,%3}, {%4,%5,%6,%7}, {%8,%9}, {%0,%1,%2,%3};"
        : "+f"(d[0]), "+f"(d[1]), "+f"(d[2]), "+f"(d[3])
        : "r"(a[0]), "r"(a[1]), "r"(a[2]), "r"(a[3]), "r"(b[0]), "r"(b[1]));
}
__device__ __forceinline__ void mma_f16(float* d, const uint32_t* a, uint32_t b0, uint32_t b1) {
    asm volatile(
        "mma.sync.aligned.m16n8k16.row.col.f32.f16.f16.f32 "
        "{%0,%1,%2,%3}, {%4,%5,%6,%7}, {%8,%9}, {%0,%1,%2,%3};"
        : "+f"(d[0]), "+f"(d[1]), "+f"(d[2]), "+f"(d[3])
        : "r"(a[0]), "r"(a[1]), "r"(a[2]), "r"(a[3]), "r"(b0), "r"(b1));
}
#define CP_ASYNC16(dst, src) \
    asm volatile("cp.async.cg.shared.global [%0], [%1], 16;" :: "r"(dst), "l"(src))
#define CP_COMMIT() asm volatile("cp.async.commit_group;")
#define CP_WAIT2()  asm volatile("cp.async.wait_group 2;")

__device__ __forceinline__ uint32_t pack_hi(float x, float y) {
    return ((uint32_t)__bfloat16_as_ushort(__float2bfloat16(y)) << 16) |
           __bfloat16_as_ushort(__float2bfloat16(x));
}
__device__ __forceinline__ uint32_t pack_lo(float x, float y) {
    float hx = __bfloat162float(__float2bfloat16(x));
    float hy = __bfloat162float(__float2bfloat16(y));
    return ((uint32_t)__bfloat16_as_ushort(__float2bfloat16(y - hy)) << 16) |
           __bfloat16_as_ushort(__float2bfloat16(x - hx));
}
__device__ __forceinline__ uint32_t pack_h16(float x, float y) {
    __half2 h = __floats2half2_rn(x, y);
    return *(uint32_t*)&h;
}

// fast exp on the FMA pipe (avoids MUFU bottleneck); valid for x <= ~80
__device__ __forceinline__ float fexp(float x) {
    float t = fmaxf(x, -80.0f) * 1.442695041f;
    float n = floorf(t);
    float f = t - n;
    float p = 0.0013276471f;
    p = p * f + 0.0096755413f;
    p = p * f + 0.0555041086f;
    p = p * f + 0.2402264923f;
    p = p * f + 0.6931471825f;
    p = p * f + 1.0f;
    return __int_as_float(((int)n << 23) + __float_as_int(p));
}

// ======================= weight transpose + split =======================
// W [K,N] fp32 (per layer, blockIdx.z) -> hi/lo [N,K] bf16
__global__ __launch_bounds__(256) void wsplit_kernel(
    const float* __restrict__ W, __nv_bfloat16* __restrict__ hi,
    __nv_bfloat16* __restrict__ lo, int K, int N)
{
    __shared__ float t[32][33];
    size_t lsz = (size_t)K * N;
    const float* Wl = W + (size_t)blockIdx.z * lsz;
    __nv_bfloat16* hil = hi + (size_t)blockIdx.z * lsz;
    __nv_bfloat16* lol = lo + (size_t)blockIdx.z * lsz;
    int n0 = blockIdx.x * 32, k0 = blockIdx.y * 32;
    int tx = threadIdx.x & 31, ty = threadIdx.x >> 5;  // 32x8
    #pragma unroll
    for (int i = 0; i < 4; i++)
        t[ty + 8 * i][tx] = Wl[(size_t)(k0 + ty + 8 * i) * N + n0 + tx];
    __syncthreads();
    #pragma unroll
    for (int i = 0; i < 4; i++) {
        float v = t[tx][ty + 8 * i];
        __nv_bfloat16 h = __float2bfloat16(v);
        __nv_bfloat16 l = __float2bfloat16(v - __bfloat162float(h));
        size_t off = (size_t)(n0 + ty + 8 * i) * K + k0 + tx;
        hil[off] = h;
        lol[off] = l;
    }
}

// W [K,N] fp32 -> [N,K] fp16 (single digit, LM head)
__global__ __launch_bounds__(256) void wsplit_f16_kernel(
    const float* __restrict__ W, __half* __restrict__ out, int K, int N)
{
    __shared__ float t[32][33];
    int n0 = blockIdx.x * 32, k0 = blockIdx.y * 32;
    int tx = threadIdx.x & 31, ty = threadIdx.x >> 5;
    #pragma unroll
    for (int i = 0; i < 4; i++)
        t[ty + 8 * i][tx] = W[(size_t)(k0 + ty + 8 * i) * N + n0 + tx];
    __syncthreads();
    #pragma unroll
    for (int i = 0; i < 4; i++) {
        float v = t[tx][ty + 8 * i];
        out[(size_t)(n0 + ty + 8 * i) * K + k0 + tx] = __float2half(v);
    }
}

// ======================= HMMA GEMM (bf16 x3 compensation) =============
// C[M,N] = A[M,K](fp32) @ W[N,K]^T (bf16 hi/lo)  (+bias,+resid,relu)
// 128x128 tile, BK=32, 256 thr, 8 warps (4m x 2n), warp tile 32x64.
// A: direct global->register fragments (no smem). B: 3-stage cp.async ring.
#define RSB 80                       // B smem row stride bytes (64 data + 16 pad)
#define BSTG (2 * 128 * RSB)         // one stage: Bh + Bl = 20480 B
#define BH_OFF(s) ((s) * BSTG)
#define BL_OFF(s) ((s) * BSTG + 128 * RSB)
#define GEMM_SMEM (3 * BSTG)         // 61440

template <int BIAS, int RELU, int RESID>
__global__ __launch_bounds__(256, 2) void gemm_mma(
    const float* __restrict__ A, const __nv_bfloat16* __restrict__ Bhi,
    const __nv_bfloat16* __restrict__ Blo, const float* __restrict__ bias,
    const float* __restrict__ resid, float* __restrict__ C, int N, int K)
{
    extern __shared__ char sm[];
    uint32_t sb = smem_u32(sm);
    int tid = threadIdx.x;
    int lane = tid & 31, wid = tid >> 5;
    int warp_m = wid >> 1, warp_n = wid & 1;
    int m0 = blockIdx.x * 128, n0 = blockIdx.y * 128;
    const int NC = K >> 5;

    float acc[2][8][4];
    #pragma unroll
    for (int t = 0; t < 2; t++)
        #pragma unroll
        for (int n = 0; n < 8; n++)
            #pragma unroll
            for (int j = 0; j < 4; j++) acc[t][n][j] = 0.f;

    const float* Abase = A + (size_t)(m0 + warp_m * 32 + (lane >> 2)) * K + (lane & 3) * 2;

    auto issueB = [&](int c, int s) {
        int k0 = c << 5;
        #pragma unroll
        for (int v = 0; v < 2; v++) {
            const __nv_bfloat16* src = v ? Blo : Bhi;
            uint32_t dstb = sb + (v ? BL_OFF(s) : BH_OFF(s));
            #pragma unroll
            for (int j = 0; j < 2; j++) {
                int fi = tid + j * 256;
                int row = fi >> 2, c16 = (fi & 3) << 3;
                const void* g = src + (size_t)(n0 + row) * K + k0 + c16;
                CP_ASYNC16(dstb + row * RSB + c16 * 2, g);
            }
        }
        CP_COMMIT();
    };

    auto compute = [&](int c, int s) {
        #pragma unroll
        for (int ks = 0; ks < 2; ks++) {
            int kbase = (c << 5) + (ks << 4);
            float2 f[2][4];
            #pragma unroll
            for (int t = 0; t < 2; t++) {
                const float* ap = Abase + (size_t)t * 16 * K + kbase;
                f[t][0] = *(const float2*)(ap);
                f[t][1] = *(const float2*)(ap + (size_t)8 * K);
                f[t][2] = *(const float2*)(ap + 8);
                f[t][3] = *(const float2*)(ap + (size_t)8 * K + 8);
            }
            uint32_t bh[8][2], bl[8][2];
            #pragma unroll
            for (int p = 0; p < 4; p++) {
                int row = warp_n * 64 + p * 16 + (lane & 7) + (((lane >> 4) & 1) << 3);
                uint32_t off = row * RSB + ks * 32 + (((lane >> 3) & 1) << 4);
                uint32_t r[4];
                ldmatrix_x4(r, sb + BH_OFF(s) + off);
                bh[2 * p][0] = r[0]; bh[2 * p][1] = r[1];
                bh[2 * p + 1][0] = r[2]; bh[2 * p + 1][1] = r[3];
                ldmatrix_x4(r, sb + BL_OFF(s) + off);
                bl[2 * p][0] = r[0]; bl[2 * p][1] = r[1];
                bl[2 * p + 1][0] = r[2]; bl[2 * p + 1][1] = r[3];
            }
            uint32_t ah[2][4], al[2][4];
            #pragma unroll
            for (int t = 0; t < 2; t++)
                #pragma unroll
                for (int j = 0; j < 4; j++) {
                    ah[t][j] = pack_hi(f[t][j].x, f[t][j].y);
                    al[t][j] = pack_lo(f[t][j].x, f[t][j].y);
                }
            #pragma unroll
            for (int t = 0; t < 2; t++)
                #pragma unroll
                for (int n = 0; n < 8; n++) {
                    mma_bf16(acc[t][n], ah[t], bh[n]);
                    mma_bf16(acc[t][n], al[t], bh[n]);
                    mma_bf16(acc[t][n], ah[t], bl[n]);
                }
        }
    };

    issueB(0, 0);
    issueB(1, 1);
    issueB(2, 2);

    for (int c = 0; c < NC; c++) {
        int s = c % 3;
        CP_WAIT2();
        __syncthreads();
        compute(c, s);
        __syncthreads();   // all warps done reading stage s before refilling it
        if (c + 3 < NC) issueB(c + 3, s);
    }

    #pragma unroll
    for (int t = 0; t < 2; t++) {
        int row0 = m0 + warp_m * 32 + t * 16 + (lane >> 2);
        #pragma unroll
        for (int n = 0; n < 8; n++) {
            int col = n0 + warp_n * 64 + n * 8 + (lane & 3) * 2;
            float b0 = 0.f, b1 = 0.f;
            if (BIAS) { b0 = bias[col]; b1 = bias[col + 1]; }
            float v0 = acc[t][n][0] + b0, v1 = acc[t][n][1] + b1;
            float v2 = acc[t][n][2] + b0, v3 = acc[t][n][3] + b1;
            size_t o0 = (size_t)row0 * N + col;
            size_t o1 = (size_t)(row0 + 8) * N + col;
            if (RESID) {
                float2 r0 = *(const float2*)(resid + o0);
                float2 r1 = *(const float2*)(resid + o1);
                v0 += r0.x; v1 += r0.y; v2 += r1.x; v3 += r1.y;
            }
            if (RELU) {
                v0 = fmaxf(v0, 0.f); v1 = fmaxf(v1, 0.f);
                v2 = fmaxf(v2, 0.f); v3 = fmaxf(v3, 0.f);
            }
            *(float2*)(C + o0) = make_float2(v0, v1);
            *(float2*)(C + o1) = make_float2(v2, v3);
        }
    }
}

// ======================= fp16 single-digit GEMM (LM head) =============
// C[M,N] = A(fp32->fp16) @ W(fp16)[N,K]^T + bias. 1 MMA per tile (3x fewer).
#define FRS 80
#define FSTG (128 * FRS)            // 10240 per stage
#define F16_SMEM (3 * FSTG)         // 30720

__global__ __launch_bounds__(256, 2) void gemm_f16(
    const float* __restrict__ A, const __half* __restrict__ Bw,
    const float* __restrict__ bias, float* __restrict__ C, int N, int K)
{
    __shared__ char sm[F16_SMEM];
    uint32_t sb = smem_u32(sm);
    int tid = threadIdx.x;
    int lane = tid & 31, wid = tid >> 5;
    int warp_m = wid >> 1, warp_n = wid & 1;
    int m0 = blockIdx.x * 128, n0 = blockIdx.y * 128;
    const int NC = K >> 5;

    float acc[2][8][4];
    #pragma unroll
    for (int t = 0; t < 2; t++)
        #pragma unroll
        for (int n = 0; n < 8; n++)
            #pragma unroll
            for (int j = 0; j < 4; j++) acc[t][n][j] = 0.f;

    const float* Abase = A + (size_t)(m0 + warp_m * 32 + (lane >> 2)) * K + (lane & 3) * 2;

    auto issueB = [&](int c, int s) {
        int k0 = c << 5;
        #pragma unroll
        for (int j = 0; j < 2; j++) {
            int fi = tid + j * 256;
            int row = fi >> 2, c16 = (fi & 3) << 4;   // 4x16B per 64B row
            const char* g = (const char*)Bw + ((size_t)(n0 + row) * K + k0) * 2 + c16;
            CP_ASYNC16(sb + s * FSTG + row * FRS + c16, g);
        }
        CP_COMMIT();
    };

    auto compute = [&](int c, int s) {
        #pragma unroll
        for (int ks = 0; ks < 2; ks++) {
            int kbase = (c << 5) + (ks << 4);
            float2 f[2][4];
            #pragma unroll
            for (int t = 0; t < 2; t++) {
                const float* ap = Abase + (size_t)t * 16 * K + kbase;
                f[t][0] = *(const float2*)(ap);
                f[t][1] = *(const float2*)(ap + (size_t)8 * K);
                f[t][2] = *(const float2*)(ap + 8);
                f[t][3] = *(const float2*)(ap + (size_t)8 * K + 8);
            }
            uint32_t bh[8][2];
            #pragma unroll
            for (int p = 0; p < 4; p++) {
                int row = warp_n * 64 + p * 16 + (lane & 7) + (((lane >> 4) & 1) << 3);
                uint32_t off = row * FRS + ks * 32 + (((lane >> 3) & 1) << 4);
                uint32_t r[4];
                ldmatrix_x4(r, sb + s * FSTG + off);
                bh[2 * p][0] = r[0]; bh[2 * p][1] = r[1];
                bh[2 * p + 1][0] = r[2]; bh[2 * p + 1][1] = r[3];
            }
            uint32_t ah[2][4];
            #pragma unroll
            for (int t = 0; t < 2; t++)
                #pragma unroll
                for (int j = 0; j < 4; j++)
                    ah[t][j] = pack_h16(f[t][j].x, f[t][j].y);
            #pragma unroll
            for (int t = 0; t < 2; t++)
                #pragma unroll
                for (int n = 0; n < 8; n++)
                    mma_f16(acc[t][n], ah[t], bh[n][0], bh[n][1]);
        }
    };

    issueB(0, 0);
    issueB(1, 1);
    issueB(2, 2);

    for (int c = 0; c < NC; c++) {
        int s = c % 3;
        CP_WAIT2();
        __syncthreads();
        compute(c, s);
        __syncthreads();
        if (c + 3 < NC) issueB(c + 3, s);
    }

    #pragma unroll
    for (int t = 0; t < 2; t++) {
        int row0 = m0 + warp_m * 32 + t * 16 + (lane >> 2);
        #pragma unroll
        for (int n = 0; n < 8; n++) {
            int col = n0 + warp_n * 64 + n * 8 + (lane & 3) * 2;
            float b0 = bias[col], b1 = bias[col + 1];
            size_t o0 = (size_t)row0 * N + col;
            size_t o1 = (size_t)(row0 + 8) * N + col;
            *(float2*)(C + o0) = make_float2(acc[t][n][0] + b0, acc[t][n][1] + b1);
            *(float2*)(C + o1) = make_float2(acc[t][n][2] + b0, acc[t][n][3] + b1);
        }
    }
}

// ======================= embedding ====================================
__global__ __launch_bounds__(256) void embed_kernel(
    const int* __restrict__ idx, const float* __restrict__ tok,
    const float* __restrict__ pos, float* __restrict__ x)
{
    int bt = blockIdx.x;
    int t = bt & (T_ - 1);
    int token = idx[bt];
    int c = threadIdx.x * 4;
    float4 tv = *(const float4*)(tok + (size_t)token * C_ + c);
    float4 pv = *(const float4*)(pos + (size_t)t * C_ + c);
    *(float4*)(x + (size_t)bt * C_ + c) =
        make_float4(tv.x + pv.x, tv.y + pv.y, tv.z + pv.z, tv.w + pv.w);
}

// ======================= layernorm ====================================
__global__ __launch_bounds__(256) void ln_kernel(
    const float* __restrict__ x, const float* __restrict__ g,
    const float* __restrict__ b, float* __restrict__ y)
{
    __shared__ float red[8];
    __shared__ float bc_mean, bc_inv;
    int row = blockIdx.x, tid = threadIdx.x;
    const float* xr = x + (size_t)row * C_;
    float4 xv = *(const float4*)(xr + tid * 4);
    float s = xv.x + xv.y + xv.z + xv.w;
    #pragma unroll
    for (int o = 16; o; o >>= 1) s += __shfl_xor_sync(0xffffffffu, s, o);
    if ((tid & 31) == 0) red[tid >> 5] = s;
    __syncthreads();
    if (tid == 0) {
        float t = 0.f;
        #pragma unroll
        for (int i = 0; i < 8; i++) t += red[i];
        bc_mean = t * (1.0f / C_);
    }
    __syncthreads();
    float mean = bc_mean;
    float d0 = xv.x - mean, d1 = xv.y - mean, d2 = xv.z - mean, d3 = xv.w - mean;
    float sq = d0 * d0 + d1 * d1 + d2 * d2 + d3 * d3;
    #pragma unroll
    for (int o = 16; o; o >>= 1) sq += __shfl_xor_sync(0xffffffffu, sq, o);
    if ((tid & 31) == 0) red[tid >> 5] = sq;
    __syncthreads();
    if (tid == 0) {
        float t = 0.f;
        #pragma unroll
        for (int i = 0; i < 8; i++) t += red[i];
        bc_inv = rsqrtf(t * (1.0f / C_) + 1e-5f);
    }
    __syncthreads();
    float inv = bc_inv;
    float4 gv = *(const float4*)(g + tid * 4);
    float4 bv = *(const float4*)(b + tid * 4);
    *(float4*)(y + (size_t)row * C_ + tid * 4) =
        make_float4(d0 * inv * gv.x + bv.x, d1 * inv * gv.y + bv.y,
                    d2 * inv * gv.z + bv.z, d3 * inv * gv.w + bv.w);
}

// ======================= causal flash attention =======================
#define ATTN_SMEM (4 * 64 * 68 * 4)
__global__ __launch_bounds__(256) void attn_kernel(
    const float* __restrict__ Q, const float* __restrict__ K,
    const float* __restrict__ V, float* __restrict__ O)
{
    extern __shared__ float smf[];
    float (*Qs)[68]  = (float(*)[68])smf;
    float (*KsT)[68] = (float(*)[68])(smf + 64 * 68);
    float (*Vs)[68]  = (float(*)[68])(smf + 2 * 64 * 68);
    float (*Ps)[68]  = (float(*)[68])(smf + 3 * 64 * 68);

    int qb = blockIdx.x;
    int bh = blockIdx.y;
    int b = bh >> 4, hh = bh & 15;
    size_t base = (size_t)b * T_ * C_ + (size_t)hh * 64;
    int tid = threadIdx.x;
    int row = tid >> 2, seg = tid & 3;
    int gq = qb * 64 + row;

    for (int i = tid; i < 64 * 16; i += 256) {
        int r = i >> 4, c4 = (i & 15) << 2;
        *(float4*)&Qs[r][c4] = *(const float4*)&Q[base + (size_t)(qb * 64 + r) * C_ + c4];
    }
    __syncthreads();

    float m = -1e30f, l = 0.f;
    float o[16];
    #pragma unroll
    for (int j = 0; j < 16; j++) o[j] = 0.f;

    for (int kb = 0; kb <= qb; kb++) {
        for (int i = tid; i < 64 * 16; i += 256) {
            int r = i >> 4, c4 = (i & 15) << 2;
            size_t goff = base + (size_t)(kb * 64 + r) * C_ + c4;
            float4 kv = *(const float4*)&K[goff];
            KsT[c4 + 0][r] = kv.x;
            KsT[c4 + 1][r] = kv.y;
            KsT[c4 + 2][r] = kv.z;
            KsT[c4 + 3][r] = kv.w;
            *(float4*)&Vs[r][c4] = *(const float4*)&V[goff];
        }
        __syncthreads();

        float sv[16];
        #pragma unroll
        for (int j = 0; j < 16; j++) sv[j] = 0.f;
        #pragma unroll 16
        for (int d = 0; d < 64; d++) {
            float qd = Qs[row][d];
            float4 k0 = *(const float4*)&KsT[d][seg * 16];
            float4 k1 = *(const float4*)&KsT[d][seg * 16 + 4];
            float4 k2 = *(const float4*)&KsT[d][seg * 16 + 8];
            float4 k3 = *(const float4*)&KsT[d][seg * 16 + 12];
            sv[0]  += qd * k0.x; sv[1]  += qd * k0.y; sv[2]  += qd * k0.z; sv[3]  += qd * k0.w;
            sv[4]  += qd * k1.x; sv[5]  += qd * k1.y; sv[6]  += qd * k1.z; sv[7]  += qd * k1.w;
            sv[8]  += qd * k2.x; sv[9]  += qd * k2.y; sv[10] += qd * k2.z; sv[11] += qd * k2.w;
            sv[12] += qd * k3.x; sv[13] += qd * k3.y; sv[14] += qd * k3.z; sv[15] += qd * k3.w;
        }
        #pragma unroll
        for (int j = 0; j < 16; j++) {
            int gk = kb * 64 + seg * 16 + j;
            sv[j] = (gk <= gq) ? sv[j] * 0.125f : -1e30f;
        }

        float tmax = sv[0];
        #pragma unroll
        for (int j = 1; j < 16; j++) tmax = fmaxf(tmax, sv[j]);
        tmax = fmaxf(tmax, __shfl_xor_sync(0xffffffffu, tmax, 1));
        tmax = fmaxf(tmax, __shfl_xor_sync(0xffffffffu, tmax, 2));
        float mnew = fmaxf(m, tmax);
        float corr = fexp(m - mnew);
        float ls = 0.f;
        #pragma unroll
        for (int j = 0; j < 16; j++) {
            float p = fexp(sv[j] - mnew);
            Ps[row][seg * 16 + j] = p;
            ls += p;
        }
        ls += __shfl_xor_sync(0xffffffffu, ls, 1);
        ls += __shfl_xor_sync(0xffffffffu, ls, 2);
        l = l * corr + ls;
        m = mnew;
        #pragma unroll
        for (int j = 0; j < 16; j++) o[j] *= corr;
        __syncwarp();

        #pragma unroll 8
        for (int kk = 0; kk < 64; kk++) {
            float p = Ps[row][kk];
            const float* vr = &Vs[kk][seg * 16];
            float4 v0 = *(const float4*)(vr);
            float4 v1 = *(const float4*)(vr + 4);
            float4 v2 = *(const float4*)(vr + 8);
            float4 v3 = *(const float4*)(vr + 12);
            o[0]  += p * v0.x; o[1]  += p * v0.y; o[2]  += p * v0.z; o[3]  += p * v0.w;
            o[4]  += p * v1.x; o[5]  += p * v1.y; o[6]  += p * v1.z; o[7]  += p * v1.w;
            o[8]  += p * v2.x; o[9]  += p * v2.y; o[10] += p * v2.z; o[11] += p * v2.w;
            o[12] += p * v3.x; o[13] += p * v3.y; o[14] += p * v3.z; o[15] += p * v3.w;
        }
        __syncthreads();
    }

    float inv = 1.0f / l;
    size_t ooff = base + (size_t)gq * C_ + seg * 16;
    *(float4*)&O[ooff]      = make_float4(o[0] * inv,  o[1] * inv,  o[2] * inv,  o[3] * inv);
    *(float4*)&O[ooff + 4]  = make_float4(o[4] * inv,  o[5] * inv,  o[6] * inv,  o[7] * inv);
    *(float4*)&O[ooff + 8]  = make_float4(o[8] * inv,  o[9] * inv,  o[10] * inv, o[11] * inv);
    *(float4*)&O[ooff + 12] = make_float4(o[12] * inv, o[13] * inv, o[14] * inv, o[15] * inv);
}

// ======================= loss =========================================
__global__ void loss_init_kernel(float* loss) { *loss = 0.f; }

__global__ __launch_bounds__(256) void loss_kernel(
    const float* __restrict__ logits, const int* __restrict__ targets,
    float* __restrict__ loss)
{
    __shared__ float red[8];
    __shared__ float bmx_s, bsum_s;
    int row = blockIdx.x, tid = threadIdx.x;
    const float4* lr4 = (const float4*)(logits + (size_t)row * V_);

    float mx = -1e30f;
    for (int i = tid; i < V_ / 4; i += 256) {
        float4 u = lr4[i];
        mx = fmaxf(mx, fmaxf(fmaxf(u.x, u.y), fmaxf(u.z, u.w)));
    }
    #pragma unroll
    for (int o = 16; o; o >>= 1) mx = fmaxf(mx, __shfl_xor_sync(0xffffffffu, mx, o));
    if ((tid & 31) == 0) red[tid >> 5] = mx;
    __syncthreads();
    if (tid == 0) {
        float t = red[0];
        #pragma unroll
        for (int i = 1; i < 8; i++) t = fmaxf(t, red[i]);
        bmx_s = t;
    }
    __syncthreads();
    float bmx = bmx_s;

    float s = 0.f;
    for (int i = tid; i < V_ / 4; i += 256) {
        float4 u = lr4[i];
        s += fexp(u.x - bmx) + fexp(u.y - bmx) + fexp(u.z - bmx) + fexp(u.w - bmx);
    }
    #pragma unroll
    for (int o = 16; o; o >>= 1) s += __shfl_xor_sync(0xffffffffu, s, o);
    if ((tid & 31) == 0) red[tid >> 5] = s;
    __syncthreads();
    if (tid == 0) {
        float t = 0.f;
        #pragma unroll
        for (int i = 0; i < 8; i++) t += red[i];
        bsum_s = t;
    }
    __syncthreads();
    if (tid == 0) {
        int tgt = targets[row];
        float lp = logits[(size_t)row * V_ + tgt] - bmx - logf(bsum_s);
        atomicAdd(loss, -lp * (1.0f / M_));
    }
}

// ======================= host =========================================
extern "C" void kernel_launch(void* const* d_in, const int* in_sizes, int n_in,
                              void* d_out, int out_size)
{
    const int*   idx     = (const int*)d_in[0];
    const int*   targets = (const int*)d_in[1];
    const float* tok     = (const float*)d_in[2];
    const float* pos     = (const float*)d_in[3];
    const float* ln1g    = (const float*)d_in[4];
    const float* ln1b    = (const float*)d_in[5];
    const float* Wq      = (const float*)d_in[6];
    const float* Wk      = (const float*)d_in[7];
    const float* Wv      = (const float*)d_in[8];
    const float* Wo      = (const float*)d_in[9];
    const float* bo      = (const float*)d_in[10];
    const float* ln2g    = (const float*)d_in[11];
    const float* ln2b    = (const float*)d_in[12];
    const float* W1      = (const float*)d_in[13];
    const float* b1      = (const float*)d_in[14];
    const float* W2      = (const float*)d_in[15];
    const float* b2      = (const float*)d_in[16];
    const float* lnfg    = (const float*)d_in[17];
    const float* lnfb    = (const float*)d_in[18];
    const float* Wlm     = (const float*)d_in[19];
    const float* blm     = (const float*)d_in[20];

    static float *x = nullptr, *h = nullptr, *big = nullptr, *lgbuf = nullptr;
    static __nv_bfloat16 *qkvo_hi, *qkvo_lo, *w1_hi, *w1_lo, *w2_hi, *w2_lo;
    static __half *wlm16;
    static bool init = false;
    if (!init) {
        cudaGetSymbolAddress((void**)&x, g_x);
        cudaGetSymbolAddress((void**)&h, g_h);
        cudaGetSymbolAddress((void**)&big, g_big);
        cudaGetSymbolAddress((void**)&lgbuf, g_logits);
        cudaGetSymbolAddress((void**)&qkvo_hi, g_qkvo_hi);
        cudaGetSymbolAddress((void**)&qkvo_lo, g_qkvo_lo);
        cudaGetSymbolAddress((void**)&w1_hi, g_w1_hi);
        cudaGetSymbolAddress((void**)&w1_lo, g_w1_lo);
        cudaGetSymbolAddress((void**)&w2_hi, g_w2_hi);
        cudaGetSymbolAddress((void**)&w2_lo, g_w2_lo);
        cudaGetSymbolAddress((void**)&wlm16, g_wlm16);
        cudaFuncSetAttribute(attn_kernel, cudaFuncAttributeMaxDynamicSharedMemorySize, ATTN_SMEM);
        cudaFuncSetAttribute(gemm_mma<0,0,0>, cudaFuncAttributeMaxDynamicSharedMemorySize, GEMM_SMEM);
        cudaFuncSetAttribute(gemm_mma<1,0,1>, cudaFuncAttributeMaxDynamicSharedMemorySize, GEMM_SMEM);
        cudaFuncSetAttribute(gemm_mma<1,1,0>, cudaFuncAttributeMaxDynamicSharedMemorySize, GEMM_SMEM);
        init = true;
    }

    const size_t NTV = (size_t)M_ * V_;
    float* logits_ptr = ((size_t)out_size >= NTV) ? (float*)d_out : lgbuf;
    float* loss_ptr = nullptr;
    if ((size_t)out_size == NTV + 1)     loss_ptr = (float*)d_out + NTV;
    else if ((size_t)out_size < NTV)     loss_ptr = (float*)d_out;

    float* qb_  = big;
    float* kb_  = big + (size_t)M_ * C_;
    float* vb_  = big + (size_t)2 * M_ * C_;
    float* att_ = big + (size_t)3 * M_ * C_;
    float* mlp_ = big;

    const size_t CC = (size_t)C_ * C_;
    const size_t LCC = (size_t)L_ * CC;

    // ---- weight prep (transpose + split / fp16 convert) ----
    wsplit_kernel<<<dim3(C_ / 32, C_ / 32, L_), 256>>>(Wq, qkvo_hi + 0 * LCC, qkvo_lo + 0 * LCC, C_, C_);
    wsplit_kernel<<<dim3(C_ / 32, C_ / 32, L_), 256>>>(Wk, qkvo_hi + 1 * LCC, qkvo_lo + 1 * LCC, C_, C_);
    wsplit_kernel<<<dim3(C_ / 32, C_ / 32, L_), 256>>>(Wv, qkvo_hi + 2 * LCC, qkvo_lo + 2 * LCC, C_, C_);
    wsplit_kernel<<<dim3(C_ / 32, C_ / 32, L_), 256>>>(Wo, qkvo_hi + 3 * LCC, qkvo_lo + 3 * LCC, C_, C_);
    wsplit_kernel<<<dim3(4 * C_ / 32, C_ / 32, L_), 256>>>(W1, w1_hi, w1_lo, C_, 4 * C_);
    wsplit_kernel<<<dim3(C_ / 32, 4 * C_ / 32, L_), 256>>>(W2, w2_hi, w2_lo, 4 * C_, C_);
    wsplit_f16_kernel<<<dim3(V_ / 32, C_ / 32), 256>>>(Wlm, wlm16, C_, V_);

    dim3 g1(M_ / 128, C_ / 128);
    dim3 g4(M_ / 128, 4 * C_ / 128);
    dim3 gl(M_ / 128, V_ / 128);
    dim3 ga(T_ / 64, B_ * H_);

    embed_kernel<<<M_, 256>>>(idx, tok, pos, x);

    for (int l = 0; l < L_; l++) {
        size_t wo = (size_t)l * CC;
        size_t w1o = (size_t)l * CC * 4;
        ln_kernel<<<M_, 256>>>(x, ln1g + (size_t)l * C_, ln1b + (size_t)l * C_, h);
        gemm_mma<0,0,0><<<g1, 256, GEMM_SMEM>>>(h, qkvo_hi + 0 * LCC + wo, qkvo_lo + 0 * LCC + wo, nullptr, nullptr, qb_, C_, C_);
        gemm_mma<0,0,0><<<g1, 256, GEMM_SMEM>>>(h, qkvo_hi + 1 * LCC + wo, qkvo_lo + 1 * LCC + wo, nullptr, nullptr, kb_, C_, C_);
        gemm_mma<0,0,0><<<g1, 256, GEMM_SMEM>>>(h, qkvo_hi + 2 * LCC + wo, qkvo_lo + 2 * LCC + wo, nullptr, nullptr, vb_, C_, C_);
        attn_kernel<<<ga, 256, ATTN_SMEM>>>(qb_, kb_, vb_, att_);
        gemm_mma<1,0,1><<<g1, 256, GEMM_SMEM>>>(att_, qkvo_hi + 3 * LCC + wo, qkvo_lo + 3 * LCC + wo, bo + (size_t)l * C_, x, x, C_, C_);
        ln_kernel<<<M_, 256>>>(x, ln2g + (size_t)l * C_, ln2b + (size_t)l * C_, h);
        gemm_mma<1,1,0><<<g4, 256, GEMM_SMEM>>>(h, w1_hi + w1o, w1_lo + w1o, b1 + (size_t)l * 4 * C_, nullptr, mlp_, 4 * C_, C_);
        gemm_mma<1,0,1><<<g1, 256, GEMM_SMEM>>>(mlp_, w2_hi + w1o, w2_lo + w1o, b2 + (size_t)l * C_, x, x, C_, 4 * C_);
    }

    ln_kernel<<<M_, 256>>>(x, lnfg, lnfb, h);
    gemm_f16<<<gl, 256>>>(h, wlm16, blm, logits_ptr, V_, C_);

    if (loss_ptr) {
        loss_init_kernel<<<1, 1>>>(loss_ptr);
        loss_kernel<<<M_, 256>>>(logits_ptr, targets, loss_ptr);
    }
}